// round 11
// baseline (speedup 1.0000x reference)
#include <cuda_runtime.h>
#include <math.h>
#include <math_constants.h>
#include <stdint.h>

// Problem dims
#define Bz  128
#define Nf  196
#define Ez  2048
#define Dz  512
#define Az  512
#define Mz  (Bz*Nf)   // 25088

// GEMM tiling
#define BM  128
#define BN  128           // 112 cols via tensor MMA + 16 cols via FFMA pipe
#define TK  32
#define KSTAGES (Ez/TK)   // 64
#define NSTG 3

// SMEM (floats): A[3][128][36], B[3][32][136], red[128]
#define A_STRIDE 36
#define B_STRIDE 136
#define A_STG (BM*A_STRIDE)          // 4608
#define B_STG (TK*B_STRIDE)          // 4352
#define OFF_A 0
#define OFF_B (NSTG*A_STG)           // 13824
#define OFF_RED (OFF_B + NSTG*B_STG) // 26880
#define SMEM_FLOATS (OFF_RED + BM)   // 27008
#define SMEM_BYTES (SMEM_FLOATS*4)   // 108032

// Scratch (device globals; no allocation allowed)
__device__ float g_att2[Bz*Az];
__device__ float g_scores[Mz];

// ---------------------------------------------------------------------------
// PTX helpers (valid for plain sm_103 target)
// ---------------------------------------------------------------------------
__device__ __forceinline__ uint32_t smem_u32(const void* p) {
    uint32_t a;
    asm("{ .reg .u64 t; cvta.to.shared.u64 t, %1; cvt.u32.u64 %0, t; }"
        : "=r"(a) : "l"(p));
    return a;
}

#define CP_ASYNC16(s, g) \
    asm volatile("cp.async.cg.shared.global [%0], [%1], 16;" :: "r"(s), "l"(g))
#define CP_COMMIT() asm volatile("cp.async.commit_group;" ::: "memory")
#define CP_WAIT(n)  asm volatile("cp.async.wait_group %0;" :: "n"(n) : "memory")

__device__ __forceinline__ void mma_tf32(float* c, const uint32_t* a,
                                         const uint32_t* b) {
    asm volatile(
        "mma.sync.aligned.m16n8k8.row.col.f32.tf32.tf32.f32 "
        "{%0,%1,%2,%3}, {%4,%5,%6,%7}, {%8,%9}, {%0,%1,%2,%3};"
        : "+f"(c[0]), "+f"(c[1]), "+f"(c[2]), "+f"(c[3])
        : "r"(a[0]), "r"(a[1]), "r"(a[2]), "r"(a[3]), "r"(b[0]), "r"(b[1]));
}

// ---------------------------------------------------------------------------
// Kernel 1: att2[b,a] = dec[b,:] @ Wd[:,a] + bd[a]; also zero g_scores
// ---------------------------------------------------------------------------
__global__ void k_att2(const float* __restrict__ dec,
                       const float* __restrict__ Wd,
                       const float* __restrict__ bd) {
    __shared__ float dec_s[Dz];
    int b = blockIdx.x, tid = threadIdx.x;
    dec_s[tid]       = dec[b*Dz + tid];
    dec_s[tid + 256] = dec[b*Dz + tid + 256];
    __syncthreads();
    for (int a0 = tid; a0 < Az; a0 += 256) {
        float acc = bd[a0];
        #pragma unroll 8
        for (int d = 0; d < Dz; d++) acc += dec_s[d] * Wd[d*Az + a0];
        g_att2[b*Az + a0] = acc;
    }
    for (int k = blockIdx.x*256 + tid; k < Mz; k += gridDim.x*256)
        g_scores[k] = 0.f;
}

// ---------------------------------------------------------------------------
// Kernel 2: HYBRID tf32 mma.sync (cols 0..111) + fp32 FFMA (cols 112..127)
// GEMM + fused tanh/Wf epilogue. Tensor pipe and FMA pipe run concurrently;
// both read the same double/triple-buffered smem tiles.
// Warps: wm = wid&3 (32 rows each), wn = wid>>2 (56 tensor cols each, 7 n8).
// FFMA: each thread owns 2 rows x 4 cols of the 128x16 FFMA slab.
// ---------------------------------------------------------------------------
__global__ __launch_bounds__(256, 2)
void k_gemm(const float* __restrict__ enc,
            const float* __restrict__ We,
            const float* __restrict__ be,
            const float* __restrict__ Wf) {
    extern __shared__ float sm[];
    const uint32_t sb = smem_u32(sm);
    const int tid  = threadIdx.x;
    const int lane = tid & 31;
    const int gid  = lane >> 2;       // 0..7
    const int tg   = lane & 3;        // 0..3
    const int wm   = (tid >> 5) & 3;  // 4 row-groups of 32
    const int wn   = (tid >> 5) >> 2; // 2 col-groups of 56
    const int n0   = blockIdx.x * BN; // n fastest -> L2 reuse of enc
    const int m0   = blockIdx.y * BM;
    // FFMA ownership: row pair + 4-col group
    const int fr   = (tid >> 2) * 2;        // rows fr, fr+1  (0..126)
    const int fcl  = 112 + (tid & 3) * 4;   // local cols fcl..fcl+3

    auto load_stage = [&](int ks, int st) {
        const int k0 = ks * TK;
        #pragma unroll
        for (int i = 0; i < 4; i++) {
            int f   = tid + i*256;
            int row = f >> 3, kq = f & 7;
            uint32_t dst = sb + (OFF_A + st*A_STG + row*A_STRIDE + kq*4)*4;
            CP_ASYNC16(dst, enc + (size_t)(m0 + row)*Ez + k0 + kq*4);
        }
        #pragma unroll
        for (int i = 0; i < 4; i++) {
            int f   = tid + i*256;
            int row = f >> 5, nq = f & 31;
            uint32_t dst = sb + (OFF_B + st*B_STG + row*B_STRIDE + nq*4)*4;
            CP_ASYNC16(dst, We + (size_t)(k0 + row)*Az + n0 + nq*4);
        }
    };

    float acc[2][7][4];     // tensor accumulators
    #pragma unroll
    for (int mt = 0; mt < 2; mt++)
        #pragma unroll
        for (int nt = 0; nt < 7; nt++)
            #pragma unroll
            for (int q = 0; q < 4; q++) acc[mt][nt][q] = 0.f;
    float facc[2][4];       // FFMA accumulators
    #pragma unroll
    for (int r = 0; r < 2; r++)
        #pragma unroll
        for (int c = 0; c < 4; c++) facc[r][c] = 0.f;

    load_stage(0, 0); CP_COMMIT();
    load_stage(1, 1); CP_COMMIT();

    int cur = 0;
    for (int ks = 0; ks < KSTAGES; ks++) {
        if (ks + 2 < KSTAGES) {
            load_stage(ks + 2, (ks + 2) % NSTG);
            CP_COMMIT();
            CP_WAIT(2);
        } else if (ks + 1 < KSTAGES) {
            CP_WAIT(1);
        } else {
            CP_WAIT(0);
        }
        __syncthreads();

        const uint32_t* Abuf = (const uint32_t*)(sm + OFF_A + cur*A_STG);
        const uint32_t* Bbuf = (const uint32_t*)(sm + OFF_B + cur*B_STG);
        const float*    Af   = sm + OFF_A + cur*A_STG;
        const float*    Bf   = sm + OFF_B + cur*B_STG;

        // --- tensor part: 14 n8 tiles over cols 0..111 ---
        #pragma unroll
        for (int k8 = 0; k8 < 4; k8++) {
            const int kb = k8 * 8;
            uint32_t af[2][4];
            #pragma unroll
            for (int mt = 0; mt < 2; mt++) {
                const uint32_t* Ab = Abuf + (wm*32 + mt*16 + gid)*A_STRIDE + kb + tg;
                af[mt][0] = Ab[0];
                af[mt][1] = Ab[8*A_STRIDE];
                af[mt][2] = Ab[4];
                af[mt][3] = Ab[8*A_STRIDE + 4];
            }
            uint32_t bfr[7][2];
            #pragma unroll
            for (int nt = 0; nt < 7; nt++) {
                const uint32_t* Bb = Bbuf + (kb + tg)*B_STRIDE + wn*56 + nt*8 + gid;
                bfr[nt][0] = Bb[0];
                bfr[nt][1] = Bb[4*B_STRIDE];
            }
            #pragma unroll
            for (int mt = 0; mt < 2; mt++)
                #pragma unroll
                for (int nt = 0; nt < 7; nt++)
                    mma_tf32(acc[mt][nt], af[mt], bfr[nt]);
        }

        // --- FFMA part: cols 112..127, full fp32, fills the idle FMA pipe ---
        #pragma unroll 8
        for (int k = 0; k < TK; k++) {
            float a0 = Af[fr*A_STRIDE + k];
            float a1 = Af[(fr + 1)*A_STRIDE + k];
            const float2* bp = (const float2*)(Bf + k*B_STRIDE + fcl);
            float2 b01 = bp[0];
            float2 b23 = bp[1];
            facc[0][0] += a0*b01.x; facc[0][1] += a0*b01.y;
            facc[0][2] += a0*b23.x; facc[0][3] += a0*b23.y;
            facc[1][0] += a1*b01.x; facc[1][1] += a1*b01.y;
            facc[1][2] += a1*b23.x; facc[1][3] += a1*b23.y;
        }

        __syncthreads();
        cur = (cur + 1) % NSTG;
    }

    // Epilogue: v = val + be[c] + att2[b,c]; p += Wf[c]*tanh(v); reduce rows.
    float* red = sm + OFF_RED;
    if (tid < BM) red[tid] = 0.f;
    __syncthreads();

    // tensor columns
    #pragma unroll
    for (int mt = 0; mt < 2; mt++) {
        #pragma unroll
        for (int r2 = 0; r2 < 2; r2++) {
            int mloc = wm*32 + mt*16 + r2*8 + gid;
            int m = m0 + mloc;
            int b = m / Nf;
            const float* at2 = g_att2 + (size_t)b*Az;
            float p = 0.f;
            #pragma unroll
            for (int nt = 0; nt < 7; nt++) {
                #pragma unroll
                for (int cc = 0; cc < 2; cc++) {
                    int c = n0 + wn*56 + nt*8 + 2*tg + cc;
                    float v = acc[mt][nt][r2*2 + cc] + be[c] + at2[c];
                    p += Wf[c] * tanhf(v);
                }
            }
            atomicAdd(&red[mloc], p);
        }
    }
    // FFMA columns
    #pragma unroll
    for (int r = 0; r < 2; r++) {
        int mloc = fr + r;
        int m = m0 + mloc;
        int b = m / Nf;
        const float* at2 = g_att2 + (size_t)b*Az;
        float p = 0.f;
        #pragma unroll
        for (int c4 = 0; c4 < 4; c4++) {
            int c = n0 + fcl + c4;
            float v = facc[r][c4] + be[c] + at2[c];
            p += Wf[c] * tanhf(v);
        }
        atomicAdd(&red[mloc], p);
    }
    __syncthreads();
    if (tid < BM) atomicAdd(&g_scores[m0 + tid], red[tid]);
}

// ---------------------------------------------------------------------------
// Kernel 3a: softmax over N per batch
// ---------------------------------------------------------------------------
__global__ void k_softmax(const float* __restrict__ bf,
                          float* __restrict__ alpha_out) {
    const int b = blockIdx.x, tid = threadIdx.x;
    __shared__ float sdata[256];
    float s = (tid < Nf) ? (g_scores[b*Nf + tid] + bf[0]) : -CUDART_INF_F;
    sdata[tid] = s; __syncthreads();
    for (int off = 128; off; off >>= 1) {
        if (tid < off) sdata[tid] = fmaxf(sdata[tid], sdata[tid + off]);
        __syncthreads();
    }
    float mx = sdata[0]; __syncthreads();
    float e = (tid < Nf) ? expf(s - mx) : 0.f;
    sdata[tid] = e; __syncthreads();
    for (int off = 128; off; off >>= 1) {
        if (tid < off) sdata[tid] += sdata[tid + off];
        __syncthreads();
    }
    float inv = 1.f / sdata[0];
    if (tid < Nf) alpha_out[b*Nf + tid] = e * inv;
}

// ---------------------------------------------------------------------------
// Kernel 3b: context[b,e] = sum_n alpha[b,n]*enc[b,n,e]. Unroll 7 (196=7*28)
// for MLP=7; grid (Bz,4) x 128 threads, one float4 column per thread.
// ---------------------------------------------------------------------------
__global__ __launch_bounds__(128)
void k_context(const float* __restrict__ enc,
               const float* __restrict__ alpha,
               float* __restrict__ ctx) {
    const int b  = blockIdx.x;
    const int e4 = blockIdx.y * 128 + threadIdx.x;   // 0..511
    __shared__ float a_s[Nf];
    for (int n = threadIdx.x; n < Nf; n += 128) a_s[n] = alpha[b*Nf + n];
    __syncthreads();
    const float4* p = (const float4*)(enc + (size_t)b*Nf*Ez) + e4;
    float4 s[7];
    #pragma unroll
    for (int i = 0; i < 7; i++) s[i] = make_float4(0.f, 0.f, 0.f, 0.f);
    #pragma unroll 2
    for (int n = 0; n < Nf; n += 7) {
        float4 v[7];
        #pragma unroll
        for (int i = 0; i < 7; i++) v[i] = p[(size_t)(n + i)*(Ez/4)];
        #pragma unroll
        for (int i = 0; i < 7; i++) {
            float a = a_s[n + i];
            s[i].x += a*v[i].x; s[i].y += a*v[i].y;
            s[i].z += a*v[i].z; s[i].w += a*v[i].w;
        }
    }
    float4 r = s[0];
    #pragma unroll
    for (int i = 1; i < 7; i++) {
        r.x += s[i].x; r.y += s[i].y; r.z += s[i].z; r.w += s[i].w;
    }
    ((float4*)ctx)[(size_t)b*(Ez/4) + e4] = r;
}

// ---------------------------------------------------------------------------
// kernel_launch: inputs in metadata order:
// 0 encoder_out [B,N,E], 1 decoder_hidden [B,D], 2 We [E,A], 3 be [A],
// 4 Wd [D,A], 5 bd [A], 6 Wf [A,1], 7 bf [1]
// output: context [B,E] then alpha [B,N,1], concatenated fp32
// ---------------------------------------------------------------------------
extern "C" void kernel_launch(void* const* d_in, const int* in_sizes, int n_in,
                              void* d_out, int out_size) {
    const float* enc = (const float*)d_in[0];
    const float* dec = (const float*)d_in[1];
    const float* We  = (const float*)d_in[2];
    const float* be  = (const float*)d_in[3];
    const float* Wd  = (const float*)d_in[4];
    const float* bd  = (const float*)d_in[5];
    const float* Wf  = (const float*)d_in[6];
    const float* bf  = (const float*)d_in[7];

    float* out   = (float*)d_out;
    float* ctx   = out;                 // [B, E]
    float* alpha = out + (size_t)Bz*Ez; // [B, N]

    static bool attr_set = false;
    if (!attr_set) {
        cudaFuncSetAttribute(k_gemm, cudaFuncAttributeMaxDynamicSharedMemorySize,
                             SMEM_BYTES);
        attr_set = true;
    }

    k_att2<<<Bz, 256>>>(dec, Wd, bd);
    k_gemm<<<dim3(Az/BN, Mz/BM), 256, SMEM_BYTES>>>(enc, We, be, Wf);
    k_softmax<<<Bz, 256>>>(bf, alpha);
    k_context<<<dim3(Bz, 4), 128>>>(enc, alpha, ctx);
}

// round 12
// speedup vs baseline: 1.1173x; 1.1173x over previous
#include <cuda_runtime.h>
#include <math.h>
#include <math_constants.h>
#include <stdint.h>

// Problem dims
#define Bz  128
#define Nf  196
#define Ez  2048
#define Dz  512
#define Az  512
#define Mz  (Bz*Nf)   // 25088

// GEMM tiling: BM x BN = 128 x 64 -> 1568 tiles (fine-grained, small wave tail)
#define BM  128
#define BN  64
#define TK  32
#define KSTAGES (Ez/TK)   // 64
#define NSTG 3

// SMEM (floats): A[3][128][36], B[3][32][72], red[128]
#define A_STRIDE 36
#define B_STRIDE 72
#define A_STG (BM*A_STRIDE)          // 4608
#define B_STG (TK*B_STRIDE)          // 2304
#define OFF_A 0
#define OFF_B (NSTG*A_STG)           // 13824
#define OFF_RED (OFF_B + NSTG*B_STG) // 20736
#define SMEM_FLOATS (OFF_RED + BM)   // 20864
#define SMEM_BYTES (SMEM_FLOATS*4)   // 83456

// Scratch (device globals; no allocation allowed)
__device__ float g_att2[Bz*Az];
__device__ float g_scores[Mz];

// ---------------------------------------------------------------------------
// PTX helpers (valid for plain sm_103 target)
// ---------------------------------------------------------------------------
__device__ __forceinline__ uint32_t smem_u32(const void* p) {
    uint32_t a;
    asm("{ .reg .u64 t; cvta.to.shared.u64 t, %1; cvt.u32.u64 %0, t; }"
        : "=r"(a) : "l"(p));
    return a;
}

#define CP_ASYNC16(s, g) \
    asm volatile("cp.async.cg.shared.global [%0], [%1], 16;" :: "r"(s), "l"(g))
#define CP_COMMIT() asm volatile("cp.async.commit_group;" ::: "memory")
#define CP_WAIT(n)  asm volatile("cp.async.wait_group %0;" :: "n"(n) : "memory")

__device__ __forceinline__ void mma_tf32(float* c, const uint32_t* a,
                                         const uint32_t* b) {
    asm volatile(
        "mma.sync.aligned.m16n8k8.row.col.f32.tf32.tf32.f32 "
        "{%0,%1,%2,%3}, {%4,%5,%6,%7}, {%8,%9}, {%0,%1,%2,%3};"
        : "+f"(c[0]), "+f"(c[1]), "+f"(c[2]), "+f"(c[3])
        : "r"(a[0]), "r"(a[1]), "r"(a[2]), "r"(a[3]), "r"(b[0]), "r"(b[1]));
}

// ---------------------------------------------------------------------------
// Kernel 1: att2[b,a] = dec[b,:] @ Wd[:,a] + bd[a]; 4 batches per CTA so Wd
// passes through L2 only 32x (was 128x). Also zeroes g_scores.
// ---------------------------------------------------------------------------
__global__ void k_att2(const float* __restrict__ dec,
                       const float* __restrict__ Wd,
                       const float* __restrict__ bd) {
    __shared__ float dec_s[4][Dz];
    const int b0 = blockIdx.x * 4, tid = threadIdx.x;
    for (int i = tid; i < 4*Dz; i += 256)
        dec_s[i >> 9][i & 511] = dec[(size_t)b0*Dz + i];
    __syncthreads();
    for (int a = tid; a < Az; a += 256) {
        float bv = bd[a];
        float a0 = bv, a1 = bv, a2 = bv, a3 = bv;
        #pragma unroll 8
        for (int d = 0; d < Dz; d++) {
            float w = Wd[d*Az + a];
            a0 += dec_s[0][d]*w; a1 += dec_s[1][d]*w;
            a2 += dec_s[2][d]*w; a3 += dec_s[3][d]*w;
        }
        g_att2[(b0+0)*Az + a] = a0;
        g_att2[(b0+1)*Az + a] = a1;
        g_att2[(b0+2)*Az + a] = a2;
        g_att2[(b0+3)*Az + a] = a3;
    }
    for (int k = blockIdx.x*256 + tid; k < Mz; k += gridDim.x*256)
        g_scores[k] = 0.f;
}

// ---------------------------------------------------------------------------
// Kernel 2: tf32 mma.sync GEMM (raw fp32 bits) + fused tanh/Wf epilogue.
// 3-stage cp.async pipeline. 8 warps: wm=wid&3 (32 rows), wn=wid>>2 (32 cols).
// ---------------------------------------------------------------------------
__global__ __launch_bounds__(256, 2)
void k_gemm(const float* __restrict__ enc,
            const float* __restrict__ We,
            const float* __restrict__ be,
            const float* __restrict__ Wf) {
    extern __shared__ float sm[];
    const uint32_t sb = smem_u32(sm);
    const int tid  = threadIdx.x;
    const int lane = tid & 31;
    const int gid  = lane >> 2;       // 0..7
    const int tg   = lane & 3;        // 0..3
    const int wm   = (tid >> 5) & 3;  // 4 row-groups of 32
    const int wn   = (tid >> 5) >> 2; // 2 col-groups of 32
    const int n0   = blockIdx.x * BN;   // n fastest -> L2 reuse of enc
    const int m0   = blockIdx.y * BM;

    auto load_stage = [&](int ks, int st) {
        const int k0 = ks * TK;
        // A: 128 rows x 32 k = 1024 16B-chunks, 4 per thread
        #pragma unroll
        for (int i = 0; i < 4; i++) {
            int f   = tid + i*256;
            int row = f >> 3, kq = f & 7;
            uint32_t dst = sb + (OFF_A + st*A_STG + row*A_STRIDE + kq*4)*4;
            CP_ASYNC16(dst, enc + (size_t)(m0 + row)*Ez + k0 + kq*4);
        }
        // B: 32 k-rows x 64 n = 512 chunks, 2 per thread
        #pragma unroll
        for (int i = 0; i < 2; i++) {
            int f   = tid + i*256;
            int row = f >> 4, nq = f & 15;
            uint32_t dst = sb + (OFF_B + st*B_STG + row*B_STRIDE + nq*4)*4;
            CP_ASYNC16(dst, We + (size_t)(k0 + row)*Az + n0 + nq*4);
        }
    };

    float acc[2][4][4];
    #pragma unroll
    for (int mt = 0; mt < 2; mt++)
        #pragma unroll
        for (int nt = 0; nt < 4; nt++)
            #pragma unroll
            for (int q = 0; q < 4; q++) acc[mt][nt][q] = 0.f;

    load_stage(0, 0); CP_COMMIT();
    load_stage(1, 1); CP_COMMIT();

    int cur = 0;
    for (int ks = 0; ks < KSTAGES; ks++) {
        if (ks + 2 < KSTAGES) {
            load_stage(ks + 2, (ks + 2) % NSTG);
            CP_COMMIT();
            CP_WAIT(2);
        } else if (ks + 1 < KSTAGES) {
            CP_WAIT(1);
        } else {
            CP_WAIT(0);
        }
        __syncthreads();

        const uint32_t* Abuf = (const uint32_t*)(sm + OFF_A + cur*A_STG);
        const uint32_t* Bbuf = (const uint32_t*)(sm + OFF_B + cur*B_STG);
        #pragma unroll
        for (int k8 = 0; k8 < 4; k8++) {
            const int kb = k8 * 8;
            uint32_t af[2][4];
            #pragma unroll
            for (int mt = 0; mt < 2; mt++) {
                const uint32_t* Ab = Abuf + (wm*32 + mt*16 + gid)*A_STRIDE + kb + tg;
                af[mt][0] = Ab[0];
                af[mt][1] = Ab[8*A_STRIDE];
                af[mt][2] = Ab[4];
                af[mt][3] = Ab[8*A_STRIDE + 4];
            }
            uint32_t bfr[4][2];
            #pragma unroll
            for (int nt = 0; nt < 4; nt++) {
                const uint32_t* Bb = Bbuf + (kb + tg)*B_STRIDE + wn*32 + nt*8 + gid;
                bfr[nt][0] = Bb[0];
                bfr[nt][1] = Bb[4*B_STRIDE];
            }
            #pragma unroll
            for (int mt = 0; mt < 2; mt++)
                #pragma unroll
                for (int nt = 0; nt < 4; nt++)
                    mma_tf32(acc[mt][nt], af[mt], bfr[nt]);
        }
        __syncthreads();
        cur = (cur + 1) % NSTG;
    }

    // Epilogue: v = acc + be[c] + att2[b,c]; p += Wf[c]*tanh(v); reduce rows.
    float* red = sm + OFF_RED;
    if (tid < BM) red[tid] = 0.f;
    __syncthreads();

    #pragma unroll
    for (int mt = 0; mt < 2; mt++) {
        #pragma unroll
        for (int r2 = 0; r2 < 2; r2++) {
            int mloc = wm*32 + mt*16 + r2*8 + gid;
            int m = m0 + mloc;
            int b = m / Nf;
            const float* at2 = g_att2 + (size_t)b*Az;
            float p = 0.f;
            #pragma unroll
            for (int nt = 0; nt < 4; nt++) {
                #pragma unroll
                for (int cc = 0; cc < 2; cc++) {
                    int c = n0 + wn*32 + nt*8 + 2*tg + cc;
                    float v = acc[mt][nt][r2*2 + cc] + be[c] + at2[c];
                    p += Wf[c] * tanhf(v);
                }
            }
            atomicAdd(&red[mloc], p);
        }
    }
    __syncthreads();
    if (tid < BM) atomicAdd(&g_scores[m0 + tid], red[tid]);
}

// ---------------------------------------------------------------------------
// Kernel 3a: softmax over N per batch
// ---------------------------------------------------------------------------
__global__ void k_softmax(const float* __restrict__ bf,
                          float* __restrict__ alpha_out) {
    const int b = blockIdx.x, tid = threadIdx.x;
    __shared__ float sdata[256];
    float s = (tid < Nf) ? (g_scores[b*Nf + tid] + bf[0]) : -CUDART_INF_F;
    sdata[tid] = s; __syncthreads();
    for (int off = 128; off; off >>= 1) {
        if (tid < off) sdata[tid] = fmaxf(sdata[tid], sdata[tid + off]);
        __syncthreads();
    }
    float mx = sdata[0]; __syncthreads();
    float e = (tid < Nf) ? expf(s - mx) : 0.f;
    sdata[tid] = e; __syncthreads();
    for (int off = 128; off; off >>= 1) {
        if (tid < off) sdata[tid] += sdata[tid + off];
        __syncthreads();
    }
    float inv = 1.f / sdata[0];
    if (tid < Nf) alpha_out[b*Nf + tid] = e * inv;
}

// ---------------------------------------------------------------------------
// Kernel 3b: context[b,e] = sum_n alpha[b,n]*enc[b,n,e].
// 256 threads: 128 columns x 2 n-halves (98 each, 98=7*14), smem reduce.
// Doubles resident warps vs the 128-thread version (latency-bound before).
// ---------------------------------------------------------------------------
__global__ __launch_bounds__(256)
void k_context(const float* __restrict__ enc,
               const float* __restrict__ alpha,
               float* __restrict__ ctx) {
    const int b    = blockIdx.x;
    const int col  = threadIdx.x & 127;
    const int half = threadIdx.x >> 7;
    const int e4   = blockIdx.y * 128 + col;   // 0..511
    __shared__ float a_s[Nf];
    __shared__ float4 part[128];
    for (int n = threadIdx.x; n < Nf; n += 256) a_s[n] = alpha[b*Nf + n];
    __syncthreads();
    const float4* p = (const float4*)(enc + (size_t)b*Nf*Ez) + e4;
    const int nbeg = half * 98;
    float4 s[7];
    #pragma unroll
    for (int i = 0; i < 7; i++) s[i] = make_float4(0.f, 0.f, 0.f, 0.f);
    for (int n = nbeg; n < nbeg + 98; n += 7) {
        float4 v[7];
        #pragma unroll
        for (int i = 0; i < 7; i++) v[i] = p[(size_t)(n + i)*(Ez/4)];
        #pragma unroll
        for (int i = 0; i < 7; i++) {
            float a = a_s[n + i];
            s[i].x += a*v[i].x; s[i].y += a*v[i].y;
            s[i].z += a*v[i].z; s[i].w += a*v[i].w;
        }
    }
    float4 r = s[0];
    #pragma unroll
    for (int i = 1; i < 7; i++) {
        r.x += s[i].x; r.y += s[i].y; r.z += s[i].z; r.w += s[i].w;
    }
    if (half) part[col] = r;
    __syncthreads();
    if (!half) {
        float4 q = part[col];
        r.x += q.x; r.y += q.y; r.z += q.z; r.w += q.w;
        ((float4*)ctx)[(size_t)b*(Ez/4) + e4] = r;
    }
}

// ---------------------------------------------------------------------------
// kernel_launch: inputs in metadata order:
// 0 encoder_out [B,N,E], 1 decoder_hidden [B,D], 2 We [E,A], 3 be [A],
// 4 Wd [D,A], 5 bd [A], 6 Wf [A,1], 7 bf [1]
// output: context [B,E] then alpha [B,N,1], concatenated fp32
// ---------------------------------------------------------------------------
extern "C" void kernel_launch(void* const* d_in, const int* in_sizes, int n_in,
                              void* d_out, int out_size) {
    const float* enc = (const float*)d_in[0];
    const float* dec = (const float*)d_in[1];
    const float* We  = (const float*)d_in[2];
    const float* be  = (const float*)d_in[3];
    const float* Wd  = (const float*)d_in[4];
    const float* bd  = (const float*)d_in[5];
    const float* Wf  = (const float*)d_in[6];
    const float* bf  = (const float*)d_in[7];

    float* out   = (float*)d_out;
    float* ctx   = out;                 // [B, E]
    float* alpha = out + (size_t)Bz*Ez; // [B, N]

    static bool attr_set = false;
    if (!attr_set) {
        cudaFuncSetAttribute(k_gemm, cudaFuncAttributeMaxDynamicSharedMemorySize,
                             SMEM_BYTES);
        attr_set = true;
    }

    k_att2<<<Bz/4, 256>>>(dec, Wd, bd);
    k_gemm<<<dim3(Az/BN, Mz/BM), 256, SMEM_BYTES>>>(enc, We, be, Wf);
    k_softmax<<<Bz, 256>>>(bf, alpha);
    k_context<<<dim3(Bz, 4), 256>>>(enc, alpha, ctx);
}

// round 14
// speedup vs baseline: 1.2624x; 1.1298x over previous
#include <cuda_runtime.h>
#include <math.h>
#include <math_constants.h>
#include <stdint.h>

// Problem dims
#define Bz  128
#define Nf  196
#define Ez  2048
#define Dz  512
#define Az  512
#define Mz  (Bz*Nf)   // 25088

// GEMM tiling (R9 config — best measured GEMM: ~390us)
#define BM  128
#define BN  128
#define TK  32
#define KSTAGES (Ez/TK)   // 64
#define NSTG 3

// SMEM (floats): A[3][128][36], B[3][32][136], red[128]
#define A_STRIDE 36
#define B_STRIDE 136
#define A_STG (BM*A_STRIDE)          // 4608
#define B_STG (TK*B_STRIDE)          // 4352
#define OFF_A 0
#define OFF_B (NSTG*A_STG)           // 13824
#define OFF_RED (OFF_B + NSTG*B_STG) // 26880
#define SMEM_FLOATS (OFF_RED + BM)   // 27008
#define SMEM_BYTES (SMEM_FLOATS*4)   // 108032

// Scratch (device globals; no allocation allowed)
__device__ float g_att2[Bz*Az];
__device__ float g_scores[Mz];

// ---------------------------------------------------------------------------
// PTX helpers (valid for plain sm_103 target)
// ---------------------------------------------------------------------------
__device__ __forceinline__ uint32_t smem_u32(const void* p) {
    uint32_t a;
    asm("{ .reg .u64 t; cvta.to.shared.u64 t, %1; cvt.u32.u64 %0, t; }"
        : "=r"(a) : "l"(p));
    return a;
}

#define CP_ASYNC16(s, g) \
    asm volatile("cp.async.cg.shared.global [%0], [%1], 16;" :: "r"(s), "l"(g))
#define CP_COMMIT() asm volatile("cp.async.commit_group;" ::: "memory")
#define CP_WAIT(n)  asm volatile("cp.async.wait_group %0;" :: "n"(n) : "memory")

__device__ __forceinline__ void mma_tf32(float* c, const uint32_t* a,
                                         const uint32_t* b) {
    asm volatile(
        "mma.sync.aligned.m16n8k8.row.col.f32.tf32.tf32.f32 "
        "{%0,%1,%2,%3}, {%4,%5,%6,%7}, {%8,%9}, {%0,%1,%2,%3};"
        : "+f"(c[0]), "+f"(c[1]), "+f"(c[2]), "+f"(c[3])
        : "r"(a[0]), "r"(a[1]), "r"(a[2]), "r"(a[3]), "r"(b[0]), "r"(b[1]));
}

// ---------------------------------------------------------------------------
// Kernel 1: att2[b,a] = dec[b,:] @ Wd[:,a] + bd[a]; 4 batches per CTA so Wd
// passes through L2 only 32x. Also zeroes g_scores.
// ---------------------------------------------------------------------------
__global__ void k_att2(const float* __restrict__ dec,
                       const float* __restrict__ Wd,
                       const float* __restrict__ bd) {
    __shared__ float dec_s[4][Dz];
    const int b0 = blockIdx.x * 4, tid = threadIdx.x;
    for (int i = tid; i < 4*Dz; i += 256)
        dec_s[i >> 9][i & 511] = dec[(size_t)b0*Dz + i];
    __syncthreads();
    for (int a = tid; a < Az; a += 256) {
        float bv = bd[a];
        float a0 = bv, a1 = bv, a2 = bv, a3 = bv;
        #pragma unroll 8
        for (int d = 0; d < Dz; d++) {
            float w = Wd[d*Az + a];
            a0 += dec_s[0][d]*w; a1 += dec_s[1][d]*w;
            a2 += dec_s[2][d]*w; a3 += dec_s[3][d]*w;
        }
        g_att2[(b0+0)*Az + a] = a0;
        g_att2[(b0+1)*Az + a] = a1;
        g_att2[(b0+2)*Az + a] = a2;
        g_att2[(b0+3)*Az + a] = a3;
    }
    for (int k = blockIdx.x*256 + tid; k < Mz; k += gridDim.x*256)
        g_scores[k] = 0.f;
}

// ---------------------------------------------------------------------------
// Kernel 2 (R9 verbatim): tf32 mma.sync GEMM (raw fp32 bits) + fused
// tanh/Wf epilogue. 3-stage cp.async pipeline.
// 8 warps: warp_m = wid&1 (64 rows), warp_n = wid>>1 (32 cols).
// ---------------------------------------------------------------------------
__global__ __launch_bounds__(256, 2)
void k_gemm(const float* __restrict__ enc,
            const float* __restrict__ We,
            const float* __restrict__ be,
            const float* __restrict__ Wf) {
    extern __shared__ float sm[];
    const uint32_t sb = smem_u32(sm);
    const int tid  = threadIdx.x;
    const int lane = tid & 31;
    const int gid  = lane >> 2;      // 0..7
    const int tg   = lane & 3;       // 0..3
    const int wm   = (tid >> 5) & 1; // warp_m
    const int wn   = (tid >> 5) >> 1;// warp_n 0..3
    const int n0   = blockIdx.x * BN;   // n fastest -> L2 reuse of enc
    const int m0   = blockIdx.y * BM;

    auto load_stage = [&](int ks, int st) {
        const int k0 = ks * TK;
        #pragma unroll
        for (int i = 0; i < 4; i++) {
            int f   = tid + i*256;
            int row = f >> 3, kq = f & 7;
            uint32_t dst = sb + (OFF_A + st*A_STG + row*A_STRIDE + kq*4)*4;
            CP_ASYNC16(dst, enc + (size_t)(m0 + row)*Ez + k0 + kq*4);
        }
        #pragma unroll
        for (int i = 0; i < 4; i++) {
            int f   = tid + i*256;
            int row = f >> 5, nq = f & 31;
            uint32_t dst = sb + (OFF_B + st*B_STG + row*B_STRIDE + nq*4)*4;
            CP_ASYNC16(dst, We + (size_t)(k0 + row)*Az + n0 + nq*4);
        }
    };

    float acc[4][4][4];
    #pragma unroll
    for (int mt = 0; mt < 4; mt++)
        #pragma unroll
        for (int nt = 0; nt < 4; nt++)
            #pragma unroll
            for (int q = 0; q < 4; q++) acc[mt][nt][q] = 0.f;

    load_stage(0, 0); CP_COMMIT();
    load_stage(1, 1); CP_COMMIT();

    int cur = 0;
    for (int ks = 0; ks < KSTAGES; ks++) {
        if (ks + 2 < KSTAGES) {
            load_stage(ks + 2, (ks + 2) % NSTG);
            CP_COMMIT();
            CP_WAIT(2);
        } else if (ks + 1 < KSTAGES) {
            CP_WAIT(1);
        } else {
            CP_WAIT(0);
        }
        __syncthreads();

        const uint32_t* Abuf = (const uint32_t*)(sm + OFF_A + cur*A_STG);
        const uint32_t* Bbuf = (const uint32_t*)(sm + OFF_B + cur*B_STG);
        #pragma unroll
        for (int k8 = 0; k8 < 4; k8++) {
            const int kb = k8 * 8;
            uint32_t af[4][4];
            #pragma unroll
            for (int mt = 0; mt < 4; mt++) {
                const uint32_t* Ab = Abuf + (wm*64 + mt*16 + gid)*A_STRIDE + kb + tg;
                af[mt][0] = Ab[0];
                af[mt][1] = Ab[8*A_STRIDE];
                af[mt][2] = Ab[4];
                af[mt][3] = Ab[8*A_STRIDE + 4];
            }
            uint32_t bfr[4][2];
            #pragma unroll
            for (int nt = 0; nt < 4; nt++) {
                const uint32_t* Bb = Bbuf + (kb + tg)*B_STRIDE + wn*32 + nt*8 + gid;
                bfr[nt][0] = Bb[0];
                bfr[nt][1] = Bb[4*B_STRIDE];
            }
            #pragma unroll
            for (int mt = 0; mt < 4; mt++)
                #pragma unroll
                for (int nt = 0; nt < 4; nt++)
                    mma_tf32(acc[mt][nt], af[mt], bfr[nt]);
        }
        __syncthreads();
        cur = (cur + 1) % NSTG;
    }

    // Epilogue: v = acc + be[c] + att2[b,c]; p += Wf[c]*tanh(v); reduce rows.
    float* red = sm + OFF_RED;
    if (tid < BM) red[tid] = 0.f;
    __syncthreads();

    #pragma unroll
    for (int mt = 0; mt < 4; mt++) {
        #pragma unroll
        for (int r2 = 0; r2 < 2; r2++) {
            int mloc = wm*64 + mt*16 + r2*8 + gid;
            int m = m0 + mloc;
            int b = m / Nf;
            const float* at2 = g_att2 + (size_t)b*Az;
            float p = 0.f;
            #pragma unroll
            for (int nt = 0; nt < 4; nt++) {
                #pragma unroll
                for (int cc = 0; cc < 2; cc++) {
                    int c = n0 + wn*32 + nt*8 + 2*tg + cc;
                    float v = acc[mt][nt][r2*2 + cc] + be[c] + at2[c];
                    p += Wf[c] * tanhf(v);
                }
            }
            atomicAdd(&red[mloc], p);
        }
    }
    __syncthreads();
    if (tid < BM) atomicAdd(&g_scores[m0 + tid], red[tid]);
}

// ---------------------------------------------------------------------------
// Kernel 3a: softmax over N per batch
// ---------------------------------------------------------------------------
__global__ void k_softmax(const float* __restrict__ bf,
                          float* __restrict__ alpha_out) {
    const int b = blockIdx.x, tid = threadIdx.x;
    __shared__ float sdata[256];
    float s = (tid < Nf) ? (g_scores[b*Nf + tid] + bf[0]) : -CUDART_INF_F;
    sdata[tid] = s; __syncthreads();
    for (int off = 128; off; off >>= 1) {
        if (tid < off) sdata[tid] = fmaxf(sdata[tid], sdata[tid + off]);
        __syncthreads();
    }
    float mx = sdata[0]; __syncthreads();
    float e = (tid < Nf) ? expf(s - mx) : 0.f;
    sdata[tid] = e; __syncthreads();
    for (int off = 128; off; off >>= 1) {
        if (tid < off) sdata[tid] += sdata[tid + off];
        __syncthreads();
    }
    float inv = 1.f / sdata[0];
    if (tid < Nf) alpha_out[b*Nf + tid] = e * inv;
}

// ---------------------------------------------------------------------------
// Kernel 3b: context[b,e] = sum_n alpha[b,n]*enc[b,n,e].
// 256 threads: 128 columns x 2 n-halves (98 each, 98=7*14), smem reduce.
// Measured 35.5us @ 75% DRAM in R12.
// ---------------------------------------------------------------------------
__global__ __launch_bounds__(256)
void k_context(const float* __restrict__ enc,
               const float* __restrict__ alpha,
               float* __restrict__ ctx) {
    const int b    = blockIdx.x;
    const int col  = threadIdx.x & 127;
    const int half = threadIdx.x >> 7;
    const int e4   = blockIdx.y * 128 + col;   // 0..511
    __shared__ float a_s[Nf];
    __shared__ float4 part[128];
    for (int n = threadIdx.x; n < Nf; n += 256) a_s[n] = alpha[b*Nf + n];
    __syncthreads();
    const float4* p = (const float4*)(enc + (size_t)b*Nf*Ez) + e4;
    const int nbeg = half * 98;
    float4 s[7];
    #pragma unroll
    for (int i = 0; i < 7; i++) s[i] = make_float4(0.f, 0.f, 0.f, 0.f);
    for (int n = nbeg; n < nbeg + 98; n += 7) {
        float4 v[7];
        #pragma unroll
        for (int i = 0; i < 7; i++) v[i] = p[(size_t)(n + i)*(Ez/4)];
        #pragma unroll
        for (int i = 0; i < 7; i++) {
            float a = a_s[n + i];
            s[i].x += a*v[i].x; s[i].y += a*v[i].y;
            s[i].z += a*v[i].z; s[i].w += a*v[i].w;
        }
    }
    float4 r = s[0];
    #pragma unroll
    for (int i = 1; i < 7; i++) {
        r.x += s[i].x; r.y += s[i].y; r.z += s[i].z; r.w += s[i].w;
    }
    if (half) part[col] = r;
    __syncthreads();
    if (!half) {
        float4 q = part[col];
        r.x += q.x; r.y += q.y; r.z += q.z; r.w += q.w;
        ((float4*)ctx)[(size_t)b*(Ez/4) + e4] = r;
    }
}

// ---------------------------------------------------------------------------
// kernel_launch: inputs in metadata order:
// 0 encoder_out [B,N,E], 1 decoder_hidden [B,D], 2 We [E,A], 3 be [A],
// 4 Wd [D,A], 5 bd [A], 6 Wf [A,1], 7 bf [1]
// output: context [B,E] then alpha [B,N,1], concatenated fp32
// ---------------------------------------------------------------------------
extern "C" void kernel_launch(void* const* d_in, const int* in_sizes, int n_in,
                              void* d_out, int out_size) {
    const float* enc = (const float*)d_in[0];
    const float* dec = (const float*)d_in[1];
    const float* We  = (const float*)d_in[2];
    const float* be  = (const float*)d_in[3];
    const float* Wd  = (const float*)d_in[4];
    const float* bd  = (const float*)d_in[5];
    const float* Wf  = (const float*)d_in[6];
    const float* bf  = (const float*)d_in[7];

    float* out   = (float*)d_out;
    float* ctx   = out;                 // [B, E]
    float* alpha = out + (size_t)Bz*Ez; // [B, N]

    static bool attr_set = false;
    if (!attr_set) {
        cudaFuncSetAttribute(k_gemm, cudaFuncAttributeMaxDynamicSharedMemorySize,
                             SMEM_BYTES);
        attr_set = true;
    }

    k_att2<<<Bz/4, 256>>>(dec, Wd, bd);
    k_gemm<<<dim3(Az/BN, Mz/BM), 256, SMEM_BYTES>>>(enc, We, be, Wf);
    k_softmax<<<Bz, 256>>>(bf, alpha);
    k_context<<<dim3(Bz, 4), 256>>>(enc, alpha, ctx);
}